// round 9
// baseline (speedup 1.0000x reference)
#include <cuda_runtime.h>

#define HH 512
#define WW 512
#define TX 32
#define TY 32
#define NTH 384
#define RXW 44                   // res float2-word columns (x: ox-8 .. ox+35)
#define PR 21                    // pair-rows: 42 rows (y: oy-4 .. oy+37) / 2

// shifted[i,j] = src[i+di, j+dj]
__device__ __constant__ int c_di[8] = { 1, 1, 1, 0, 0, -1, -1, -1 };
__device__ __constant__ int c_dj[8] = { 1, 0,-1, 1,-1,  1,  0, -1 };

#define DI0 1
#define DI1 1
#define DI2 1
#define DI3 0
#define DI4 0
#define DI5 (-1)
#define DI6 (-1)
#define DI7 (-1)
#define DJ0 1
#define DJ1 0
#define DJ2 (-1)
#define DJ3 1
#define DJ4 (-1)
#define DJ5 1
#define DJ6 0
#define DJ7 (-1)

__device__ __forceinline__ float4 ld4_guard(const float* __restrict__ plane,
                                            int gy, int gx)
{
    float4 v = make_float4(0.f, 0.f, 0.f, 0.f);
    if ((unsigned)gy < HH) {
        const float* __restrict__ row = plane + (size_t)gy * WW;
        if ((unsigned)gx <= (unsigned)(WW - 4)) {
            v = *reinterpret_cast<const float4*>(row + gx);   // gx ≡ 0 mod 4
        } else {
            if ((unsigned)(gx + 0) < WW) v.x = __ldg(row + gx + 0);
            if ((unsigned)(gx + 1) < WW) v.y = __ldg(row + gx + 1);
            if ((unsigned)(gx + 2) < WW) v.z = __ldg(row + gx + 2);
            if ((unsigned)(gx + 3) < WW) v.w = __ldg(row + gx + 3);
        }
    }
    return v;
}

// One propagation step for a 4-row strip: gather neighbors from rc, update val.
__device__ __forceinline__ void prop_step(const float2* __restrict__ rc,
                                          int p0, int rx,
                                          const float g[4][8],
                                          const float bias[4],
                                          float val[4])
{
    const float* __restrict__ rcf = reinterpret_cast<const float*>(rc);
    float2 a0 = rc[(p0 + 0) * RXW + rx - 1];
    float2 a1 = rc[(p0 + 1) * RXW + rx - 1];
    float2 a2 = rc[(p0 + 2) * RXW + rx - 1];
    float2 b0 = rc[(p0 + 0) * RXW + rx + 1];
    float2 b1 = rc[(p0 + 1) * RXW + rx + 1];
    float2 b2 = rc[(p0 + 2) * RXW + rx + 1];
    float L[6] = { a0.x, a0.y, a1.x, a1.y, a2.x, a2.y };
    float R[6] = { b0.x, b0.y, b1.x, b1.y, b2.x, b2.y };
    float C[6];
    C[0] = rcf[((p0 + 0) * RXW + rx) * 2 + 0];   // row 4sy
    C[5] = rcf[((p0 + 2) * RXW + rx) * 2 + 1];   // row 4sy+5
    C[1] = val[0]; C[2] = val[1]; C[3] = val[2]; C[4] = val[3];

    float nv[4];
    #pragma unroll
    for (int r = 0; r < 4; r++) {
        float s = bias[r];
        s += g[r][0] * R[r + 2];
        s += g[r][1] * C[r + 2];
        s += g[r][2] * L[r + 2];
        s += g[r][3] * R[r + 1];
        s += g[r][4] * L[r + 1];
        s += g[r][5] * R[r];
        s += g[r][6] * C[r];
        s += g[r][7] * L[r];
        nv[r] = s;
    }
    #pragma unroll
    for (int r = 0; r < 4; r++) val[r] = nv[r];
}

__global__ __launch_bounds__(NTH, 3)
void affinity_fused(const float* __restrict__ guid,
                    const float* __restrict__ blur,
                    float* __restrict__ out)
{
    // fp32 exchange buffers: word (p, c) = float2(row 2p, row 2p+1) at col c
    __shared__ float2 res[2][PR * RXW];

    const int tid = threadIdx.x;
    const int b   = blockIdx.z;
    const int txi = blockIdx.x;
    const int tyi = blockIdx.y;
    const int ox  = txi * TX;
    const int oy  = tyi * TY;
    const bool edge = (txi == 0) | (txi == 15) | (tyi == 0) | (tyi == 15);

    const float* __restrict__ blurb = blur + (size_t)b * HH * WW;
    const float* __restrict__ guidb = guid + (size_t)b * 8 * HH * WW;

    // ---- Warp-aligned strip mapping ----
    // warps 0..9: strip row = warp id, cols x = ox + lane (output-aligned, 128B)
    // warps 10..11: 6 halo cols (x = ox-3..ox-1, ox+32..ox+34) x 10 rows
    const int wid  = tid >> 5;
    const int lane = tid & 31;
    const bool mainw = wid < 10;
    int sy, sx;
    bool active;
    if (mainw) {
        sy = wid; sx = lane + 3; active = true;
    } else {
        int t = tid - 320;
        active = t < 60;
        int tt = active ? t : 0;
        sy = tt / 6;
        int c = tt - 6 * sy;
        sx = (c < 3) ? c : (32 + c);      // 0,1,2 or 35,36,37
    }
    const int x   = ox - 3 + sx;          // global x of strip
    const int y0  = oy - 3 + sy * 4;      // global y of strip top
    const int rx  = sx + 5;               // res col (base ox-8)
    const int p0  = 2 * sy;               // first pair-row of strip

    float g[4][8];
    float raw[4];

    if (!edge) {
        // ============== interior fast path (no guards) ==============
        // Gate + raw LDGs first: longest-latency loads front-loaded.
        {
            const float* __restrict__ gb = guidb + (size_t)y0 * WW + x;
            #pragma unroll
            for (int r = 0; r < 4; r++) {
                const float* __restrict__ gr = gb + r * WW;
                g[r][0] = __ldg(gr + 0 * HH * WW + DI0 * WW + DJ0);
                g[r][1] = __ldg(gr + 1 * HH * WW + DI1 * WW + DJ1);
                g[r][2] = __ldg(gr + 2 * HH * WW + DI2 * WW + DJ2);
                g[r][3] = __ldg(gr + 3 * HH * WW + DI3 * WW + DJ3);
                g[r][4] = __ldg(gr + 4 * HH * WW + DI4 * WW + DJ4);
                g[r][5] = __ldg(gr + 5 * HH * WW + DI5 * WW + DJ5);
                g[r][6] = __ldg(gr + 6 * HH * WW + DI6 * WW + DJ6);
                g[r][7] = __ldg(gr + 7 * HH * WW + DI7 * WW + DJ7);
            }
            const float* __restrict__ rb = blurb + (size_t)y0 * WW + x;
            raw[0] = __ldg(rb + 0 * WW);
            raw[1] = __ldg(rb + 1 * WW);
            raw[2] = __ldg(rb + 2 * WW);
            raw[3] = __ldg(rb + 3 * WW);
        }
        #pragma unroll
        for (int i = tid; i < PR * 11; i += NTH) {
            int p = i / 11, q = i % 11;
            const float* __restrict__ base =
                blurb + (size_t)(oy - 4 + 2 * p) * WW + (ox - 8) + 4 * q;
            float4 a  = *reinterpret_cast<const float4*>(base);
            float4 bb = *reinterpret_cast<const float4*>(base + WW);
            float4 s0 = make_float4(a.x, bb.x, a.y, bb.y);
            float4 s1 = make_float4(a.z, bb.z, a.w, bb.w);
            int o = p * RXW + 4 * q;
            *reinterpret_cast<float4*>(&res[0][o])     = s0;
            *reinterpret_cast<float4*>(&res[0][o + 2]) = s1;
            // buf1: only pair-rows 0 and 20 are read before being overwritten
            if (p == 0 || p == PR - 1) {
                *reinterpret_cast<float4*>(&res[1][o])     = s0;
                *reinterpret_cast<float4*>(&res[1][o + 2]) = s1;
            }
        }
    } else {
        // ======== edge path: clamped addresses + float masks ========
        const int xc = min(max(x, 0), WW - 1);
        #pragma unroll
        for (int r = 0; r < 4; r++) {
            int y  = y0 + r;
            int yc = min(max(y, 0), HH - 1);
            bool pin = ((unsigned)y < HH) & ((unsigned)x < WW);
            float rv = __ldg(&blurb[(size_t)yc * WW + xc]);
            raw[r] = pin ? rv : 0.0f;
            #pragma unroll
            for (int k = 0; k < 8; k++) {
                int yy = y + c_di[k];
                int xx = x + c_dj[k];
                int yyc = min(max(yy, 0), HH - 1);
                int xxc = min(max(xx, 0), WW - 1);
                float v = __ldg(&guidb[((size_t)k * HH + yyc) * WW + xxc]);
                bool m = pin & ((unsigned)yy < HH) & ((unsigned)xx < WW);
                g[r][k] = m ? v : 0.0f;
            }
        }
        #pragma unroll
        for (int i = tid; i < PR * 11; i += NTH) {
            int p = i / 11, q = i % 11;
            float4 a  = ld4_guard(blurb, oy - 4 + 2 * p, ox - 8 + 4 * q);
            float4 bb = ld4_guard(blurb, oy - 3 + 2 * p, ox - 8 + 4 * q);
            float4 s0 = make_float4(a.x, bb.x, a.y, bb.y);
            float4 s1 = make_float4(a.z, bb.z, a.w, bb.w);
            int o = p * RXW + 4 * q;
            *reinterpret_cast<float4*>(&res[0][o])     = s0;
            *reinterpret_cast<float4*>(&res[0][o + 2]) = s1;
            if (p == 0 || p == PR - 1) {
                *reinterpret_cast<float4*>(&res[1][o])     = s0;
                *reinterpret_cast<float4*>(&res[1][o + 2]) = s1;
            }
        }
    }

    // ---- gate normalization (no smem dependency -> before barrier) ----
    float bias[4], val[4];
    #pragma unroll
    for (int r = 0; r < 4; r++) {
        float a = 0.f;
        #pragma unroll
        for (int k = 0; k < 8; k++) a += fabsf(g[r][k]);
        float inva = (a > 0.f) ? __fdividef(1.0f, a) : 0.0f;
        float gs = 0.f;
        #pragma unroll
        for (int k = 0; k < 8; k++) { g[r][k] *= inva; gs += g[r][k]; }
        bias[r] = (1.0f - gs) * raw[r];
        val[r]  = raw[r];
    }
    __syncthreads();

    // ---- iterations 0..2: compute, store, barrier ----
    #pragma unroll
    for (int t = 0; t < 3; t++) {
        prop_step(res[t & 1], p0, rx, g, bias, val);
        if (active) {
            float2* __restrict__ rn = res[(t & 1) ^ 1];
            float*  __restrict__ rnf = reinterpret_cast<float*>(rn);
            // row 4sy+1 -> hi float of word (p0, rx); lo owned by strip sy-1
            rnf[((p0 + 0) * RXW + rx) * 2 + 1] = val[0];
            // rows 4sy+2, 4sy+3 -> full word (p0+1, rx), exclusively owned
            rn[(p0 + 1) * RXW + rx] = make_float2(val[1], val[2]);
            // row 4sy+4 -> lo float of word (p0+2, rx)
            rnf[((p0 + 2) * RXW + rx) * 2 + 0] = val[3];
        }
        __syncthreads();
    }

    // ---- final iteration + output: only warps that produce output rows ----
    // (strip 9 covers gate rows 36..39 and halo warps cover cols outside the
    //  inner 32x32 -> their t=3 values are never read by anyone)
    if (mainw && wid < 9) {
        prop_step(res[1], p0, rx, g, bias, val);
        float* __restrict__ outb = out + (size_t)b * HH * WW;
        #pragma unroll
        for (int r = 0; r < 4; r++) {
            int gy = sy * 4 + r;
            if (gy >= 3 && gy < 3 + TY)        // uniform per warp
                outb[(y0 + r) * WW + x] = val[r];
        }
    }
}

extern "C" void kernel_launch(void* const* d_in, const int* in_sizes, int n_in,
                              void* d_out, int out_size)
{
    const float* guid = (const float*)d_in[0];
    const float* blur = (const float*)d_in[1];
    int gsz = in_sizes[0];
    int bsz = in_sizes[1];
    if (n_in >= 2 && gsz < bsz) {   // defensive: handle swapped order
        const float* tmp = guid; guid = blur; blur = tmp;
        int t = gsz; gsz = bsz; bsz = t;
    }
    int batch = bsz / (HH * WW);

    dim3 grid(16, 16, batch);
    affinity_fused<<<grid, NTH>>>(guid, blur, (float*)d_out);
}

// round 10
// speedup vs baseline: 1.1393x; 1.1393x over previous
#include <cuda_runtime.h>
#include <cuda_fp16.h>

#define HH 512
#define WW 512
#define TX 32
#define TY 32
#define NTH 384
#define RXW 44                   // res word columns (x: ox-8 .. ox+35)
#define PR 21                    // pair-rows: 42 rows (y: oy-4 .. oy+37) / 2

// shifted[i,j] = src[i+di, j+dj]
__device__ __constant__ int c_di[8] = { 1, 1, 1, 0, 0, -1, -1, -1 };
__device__ __constant__ int c_dj[8] = { 1, 0,-1, 1,-1,  1,  0, -1 };

#define DI0 1
#define DI1 1
#define DI2 1
#define DI3 0
#define DI4 0
#define DI5 (-1)
#define DI6 (-1)
#define DI7 (-1)
#define DJ0 1
#define DJ1 0
#define DJ2 (-1)
#define DJ3 1
#define DJ4 (-1)
#define DJ5 1
#define DJ6 0
#define DJ7 (-1)

__device__ __forceinline__ unsigned int pack2(float lo, float hi) {
    __half2 h = __halves2half2(__float2half_rn(lo), __float2half_rn(hi));
    return *reinterpret_cast<unsigned int*>(&h);
}
__device__ __forceinline__ float2 unpack2(unsigned int w) {
    __half2 h;
    *reinterpret_cast<unsigned int*>(&h) = w;
    return __half22float2(h);
}

__device__ __forceinline__ float4 ld4_guard(const float* __restrict__ plane,
                                            int gy, int gx)
{
    float4 v = make_float4(0.f, 0.f, 0.f, 0.f);
    if ((unsigned)gy < HH) {
        const float* __restrict__ row = plane + (size_t)gy * WW;
        if ((unsigned)gx <= (unsigned)(WW - 4)) {
            v = *reinterpret_cast<const float4*>(row + gx);   // gx ≡ 0 mod 4
        } else {
            if ((unsigned)(gx + 0) < WW) v.x = __ldg(row + gx + 0);
            if ((unsigned)(gx + 1) < WW) v.y = __ldg(row + gx + 1);
            if ((unsigned)(gx + 2) < WW) v.z = __ldg(row + gx + 2);
            if ((unsigned)(gx + 3) < WW) v.w = __ldg(row + gx + 3);
        }
    }
    return v;
}

// One propagation step for a 4-row strip (fp16 exchange, fp32 math).
__device__ __forceinline__ void prop_step(const unsigned int* __restrict__ rc,
                                          int p0, int rx,
                                          const float g[4][8],
                                          const float bias[4],
                                          float val[4])
{
    const __half* __restrict__ rch = reinterpret_cast<const __half*>(rc);
    float2 a0 = unpack2(rc[(p0 + 0) * RXW + rx - 1]);
    float2 a1 = unpack2(rc[(p0 + 1) * RXW + rx - 1]);
    float2 a2 = unpack2(rc[(p0 + 2) * RXW + rx - 1]);
    float2 b0 = unpack2(rc[(p0 + 0) * RXW + rx + 1]);
    float2 b1 = unpack2(rc[(p0 + 1) * RXW + rx + 1]);
    float2 b2 = unpack2(rc[(p0 + 2) * RXW + rx + 1]);
    float L[6] = { a0.x, a0.y, a1.x, a1.y, a2.x, a2.y };
    float R[6] = { b0.x, b0.y, b1.x, b1.y, b2.x, b2.y };
    float C[6];
    C[0] = __half2float(rch[((p0 + 0) * RXW + rx) * 2 + 0]);   // row 4sy
    C[5] = __half2float(rch[((p0 + 2) * RXW + rx) * 2 + 1]);   // row 4sy+5
    C[1] = val[0]; C[2] = val[1]; C[3] = val[2]; C[4] = val[3];

    float nv[4];
    #pragma unroll
    for (int r = 0; r < 4; r++) {
        float s = bias[r];
        s += g[r][0] * R[r + 2];
        s += g[r][1] * C[r + 2];
        s += g[r][2] * L[r + 2];
        s += g[r][3] * R[r + 1];
        s += g[r][4] * L[r + 1];
        s += g[r][5] * R[r];
        s += g[r][6] * C[r];
        s += g[r][7] * L[r];
        nv[r] = s;
    }
    #pragma unroll
    for (int r = 0; r < 4; r++) val[r] = nv[r];
}

__global__ __launch_bounds__(NTH, 3)
void affinity_fused(const float* __restrict__ guid,
                    const float* __restrict__ blur,
                    float* __restrict__ out)
{
    // fp16 exchange buffers: word (p, c) = half2(row 2p, row 2p+1) at col c
    __shared__ unsigned int res[2][PR * RXW];

    const int tid = threadIdx.x;
    const int b   = blockIdx.z;
    const int txi = blockIdx.x;
    const int tyi = blockIdx.y;
    const int ox  = txi * TX;
    const int oy  = tyi * TY;
    const bool edge = (txi == 0) | (txi == 15) | (tyi == 0) | (tyi == 15);

    const float* __restrict__ blurb = blur + (size_t)b * HH * WW;
    const float* __restrict__ guidb = guid + (size_t)b * 8 * HH * WW;

    // ---- Warp-aligned strip mapping ----
    // warps 0..9: strip row = warp id, cols x = ox + lane (output-aligned, 128B)
    // warps 10..11: 6 halo cols (x = ox-3..ox-1, ox+32..ox+34) x 10 rows
    const int wid  = tid >> 5;
    const int lane = tid & 31;
    const bool mainw = wid < 10;
    int sy, sx;
    bool active;
    if (mainw) {
        sy = wid; sx = lane + 3; active = true;
    } else {
        int t = tid - 320;
        active = t < 60;
        int tt = active ? t : 0;
        sy = tt / 6;
        int c = tt - 6 * sy;
        sx = (c < 3) ? c : (32 + c);      // 0,1,2 or 35,36,37
    }
    const int x   = ox - 3 + sx;          // global x of strip
    const int y0  = oy - 3 + sy * 4;      // global y of strip top
    const int rx  = sx + 5;               // res col (base ox-8)
    const int p0  = 2 * sy;               // first pair-row of strip

    float g[4][8];
    float raw[4];

    if (!edge) {
        // ============== interior fast path (no guards) ==============
        // Gate + raw LDGs first: longest-latency loads front-loaded.
        {
            const float* __restrict__ gb = guidb + (size_t)y0 * WW + x;
            #pragma unroll
            for (int r = 0; r < 4; r++) {
                const float* __restrict__ gr = gb + r * WW;
                g[r][0] = __ldg(gr + 0 * HH * WW + DI0 * WW + DJ0);
                g[r][1] = __ldg(gr + 1 * HH * WW + DI1 * WW + DJ1);
                g[r][2] = __ldg(gr + 2 * HH * WW + DI2 * WW + DJ2);
                g[r][3] = __ldg(gr + 3 * HH * WW + DI3 * WW + DJ3);
                g[r][4] = __ldg(gr + 4 * HH * WW + DI4 * WW + DJ4);
                g[r][5] = __ldg(gr + 5 * HH * WW + DI5 * WW + DJ5);
                g[r][6] = __ldg(gr + 6 * HH * WW + DI6 * WW + DJ6);
                g[r][7] = __ldg(gr + 7 * HH * WW + DI7 * WW + DJ7);
            }
            const float* __restrict__ rb = blurb + (size_t)y0 * WW + x;
            raw[0] = __ldg(rb + 0 * WW);
            raw[1] = __ldg(rb + 1 * WW);
            raw[2] = __ldg(rb + 2 * WW);
            raw[3] = __ldg(rb + 3 * WW);
        }
        #pragma unroll
        for (int i = tid; i < PR * 11; i += NTH) {
            int p = i / 11, q = i % 11;
            const float* __restrict__ base =
                blurb + (size_t)(oy - 4 + 2 * p) * WW + (ox - 8) + 4 * q;
            float4 a  = *reinterpret_cast<const float4*>(base);
            float4 bb = *reinterpret_cast<const float4*>(base + WW);
            unsigned int w0 = pack2(a.x, bb.x), w1 = pack2(a.y, bb.y);
            unsigned int w2 = pack2(a.z, bb.z), w3 = pack2(a.w, bb.w);
            int o = p * RXW + 4 * q;
            res[0][o+0] = w0; res[0][o+1] = w1; res[0][o+2] = w2; res[0][o+3] = w3;
            // buf1: only pair-rows 0 and 20 are read before being overwritten
            if (p == 0 || p == PR - 1) {
                res[1][o+0] = w0; res[1][o+1] = w1; res[1][o+2] = w2; res[1][o+3] = w3;
            }
        }
    } else {
        // ======== edge path: clamped addresses + float masks ========
        const int xc = min(max(x, 0), WW - 1);
        #pragma unroll
        for (int r = 0; r < 4; r++) {
            int y  = y0 + r;
            int yc = min(max(y, 0), HH - 1);
            bool pin = ((unsigned)y < HH) & ((unsigned)x < WW);
            float rv = __ldg(&blurb[(size_t)yc * WW + xc]);
            raw[r] = pin ? rv : 0.0f;
            #pragma unroll
            for (int k = 0; k < 8; k++) {
                int yy = y + c_di[k];
                int xx = x + c_dj[k];
                int yyc = min(max(yy, 0), HH - 1);
                int xxc = min(max(xx, 0), WW - 1);
                float v = __ldg(&guidb[((size_t)k * HH + yyc) * WW + xxc]);
                bool m = pin & ((unsigned)yy < HH) & ((unsigned)xx < WW);
                g[r][k] = m ? v : 0.0f;
            }
        }
        #pragma unroll
        for (int i = tid; i < PR * 11; i += NTH) {
            int p = i / 11, q = i % 11;
            float4 a  = ld4_guard(blurb, oy - 4 + 2 * p, ox - 8 + 4 * q);
            float4 bb = ld4_guard(blurb, oy - 3 + 2 * p, ox - 8 + 4 * q);
            unsigned int w0 = pack2(a.x, bb.x), w1 = pack2(a.y, bb.y);
            unsigned int w2 = pack2(a.z, bb.z), w3 = pack2(a.w, bb.w);
            int o = p * RXW + 4 * q;
            res[0][o+0] = w0; res[0][o+1] = w1; res[0][o+2] = w2; res[0][o+3] = w3;
            if (p == 0 || p == PR - 1) {
                res[1][o+0] = w0; res[1][o+1] = w1; res[1][o+2] = w2; res[1][o+3] = w3;
            }
        }
    }

    // ---- gate normalization (register-only -> hoisted before barrier) ----
    float bias[4], val[4];
    #pragma unroll
    for (int r = 0; r < 4; r++) {
        float a = 0.f;
        #pragma unroll
        for (int k = 0; k < 8; k++) a += fabsf(g[r][k]);
        float inva = (a > 0.f) ? __fdividef(1.0f, a) : 0.0f;
        float gs = 0.f;
        #pragma unroll
        for (int k = 0; k < 8; k++) { g[r][k] *= inva; gs += g[r][k]; }
        bias[r] = (1.0f - gs) * raw[r];
        val[r]  = raw[r];
    }
    __syncthreads();

    // ---- iterations 0..2: compute, store, barrier ----
    #pragma unroll
    for (int t = 0; t < 3; t++) {
        prop_step(res[t & 1], p0, rx, g, bias, val);
        if (active) {
            unsigned int* __restrict__ rn = res[(t & 1) ^ 1];
            __half* __restrict__ rh = reinterpret_cast<__half*>(rn);
            // row 4sy+1 -> hi half of word (p0, rx); lo half owned by strip sy-1
            rh[((p0 + 0) * RXW + rx) * 2 + 1] = __float2half_rn(val[0]);
            // rows 4sy+2, 4sy+3 -> full word (p0+1, rx), exclusively owned
            rn[(p0 + 1) * RXW + rx] = pack2(val[1], val[2]);
            // row 4sy+4 -> lo half of word (p0+2, rx)
            rh[((p0 + 2) * RXW + rx) * 2 + 0] = __float2half_rn(val[3]);
        }
        __syncthreads();
    }

    // ---- final iteration + output: only warps whose values are read ----
    // (strip 9 covers gate rows 36..39; halo warps cover cols outside the
    //  inner 32x32 -> their t=3 values are never consumed. No barrier after
    //  t=3, so skipping them is race-free.)
    if (wid < 9) {
        prop_step(res[1], p0, rx, g, bias, val);
        float* __restrict__ outb = out + (size_t)b * HH * WW;
        #pragma unroll
        for (int r = 0; r < 4; r++) {
            int gy = sy * 4 + r;
            if (gy >= 3 && gy < 3 + TY)        // uniform per warp
                outb[(y0 + r) * WW + x] = val[r];
        }
    }
}

extern "C" void kernel_launch(void* const* d_in, const int* in_sizes, int n_in,
                              void* d_out, int out_size)
{
    const float* guid = (const float*)d_in[0];
    const float* blur = (const float*)d_in[1];
    int gsz = in_sizes[0];
    int bsz = in_sizes[1];
    if (n_in >= 2 && gsz < bsz) {   // defensive: handle swapped order
        const float* tmp = guid; guid = blur; blur = tmp;
        int t = gsz; gsz = bsz; bsz = t;
    }
    int batch = bsz / (HH * WW);

    dim3 grid(16, 16, batch);
    affinity_fused<<<grid, NTH>>>(guid, blur, (float*)d_out);
}